// round 15
// baseline (speedup 1.0000x reference)
#include <cuda_runtime.h>
#include <math.h>

// Problem constants (features [8,64,100000], coords [8,3,100000], R=32)
constexpr int B = 8;
constexpr int C = 64;
constexpr int N = 100000;
constexpr int R = 32;
constexpr int V = R * R * R;   // 32768
constexpr int BP = 128;        // points per scatter block
constexpr int CHUNK = 32;      // points staged per chunk
constexpr int RB = 48;         // mean+radius blocks per batch
constexpr int RADP = 9;        // points per thread (48*256*9 >= N)
constexpr int MR_BLKS  = B * RB;                 // 384
constexpr int ZERO_BLKS = (B * V) / 512;         // 512 (64 rows per warp)
// grid = 896 blocks @ 8 blocks/SM (27KB smem, <=32 regs) -> ONE WAVE

// Scratch (allocation-free rule: __device__ globals). Zero-initialized at
// module load. The guarded zero keeps the invariant "rows with count==0 are
// all-zero" across graph replays by clearing exactly the dirty rows.
__device__ float        g_scratch[(size_t)B * V * C];  // [b][voxel][c]  64 MB
__device__ int          g_count[B * V];
__device__ float        g_meanpart[B * 3 * RB];
__device__ float        g_mean[B * 3];
__device__ unsigned int g_radbits[B];
__device__ unsigned int g_mdone[B];    // mean partials published per batch
__device__ unsigned int g_rdone[B];    // finished blocks per batch

// ---------------------------------------------------------------------------
// One fused launch, two block roles, sized for ONE WAVE (896 < 1184 resident):
//   [0, MR_BLKS)  single-pass mean+radius: coords staged once into SMEM
//                 (27KB, conflict-free [3][RADP][256]), mean partial
//                 published, spin for the batch's 48 partials (all MR blocks
//                 co-resident -> safe), then radius max from the SMEM stash
//                 (no global coord re-read). SMEM stash instead of register
//                 arrays keeps regs ~32 -> 8 blocks/SM.
//   [MR_BLKS, +ZERO_BLKS)  clear dirty scratch rows + counts (warp/64 rows).
// Mean = fixed-order serial sum of 48 partials (deterministic); radius via
// order-independent atomicMax; counters reset by last finisher per batch.
__global__ __launch_bounds__(256, 8) void prep_kernel(const float* __restrict__ coords) {
    __shared__ float sc[3][RADP][256];   // 27 KB coord stash (MR role only)
    const int bx = blockIdx.x;
    const int t  = threadIdx.x;

    if (bx < MR_BLKS) {            // ---- mean + radius, one coord pass ----
        const int b    = bx / RB;
        const int part = bx % RB;
        const float* px = coords + (size_t)b * 3 * N;

        float sx = 0.f, sy = 0.f, sz = 0.f;
        const int i0 = part * 256 + t;
#pragma unroll
        for (int k = 0; k < RADP; k++) {
            const int i = i0 + k * (RB * 256);
            const bool v = i < N;
            float x = v ? px[i]         : 0.f;
            float y = v ? px[i + N]     : 0.f;
            float z = v ? px[i + 2 * N] : 0.f;
            sc[0][k][t] = x; sc[1][k][t] = y; sc[2][k][t] = z;
            sx += x; sy += y; sz += z;
        }
#pragma unroll
        for (int o = 16; o; o >>= 1) {
            sx += __shfl_xor_sync(0xffffffffu, sx, o);
            sy += __shfl_xor_sync(0xffffffffu, sy, o);
            sz += __shfl_xor_sync(0xffffffffu, sz, o);
        }
        __shared__ float sh[3][8];
        __shared__ float smean[3];
        const int lane = t & 31, w = t >> 5;
        if (lane == 0) { sh[0][w] = sx; sh[1][w] = sy; sh[2][w] = sz; }
        __syncthreads();

        if (t == 0) {
            float ax = 0.f, ay = 0.f, az = 0.f;
            for (int i = 0; i < 8; i++) { ax += sh[0][i]; ay += sh[1][i]; az += sh[2][i]; }
            if (part == 0) g_radbits[b] = 0u;        // before publish: ordered
            g_meanpart[(b * 3 + 0) * RB + part] = ax;
            g_meanpart[(b * 3 + 1) * RB + part] = ay;
            g_meanpart[(b * 3 + 2) * RB + part] = az;
            __threadfence();
            atomicAdd(&g_mdone[b], 1u);              // publish
            while (atomicAdd(&g_mdone[b], 0u) < (unsigned)RB)
                __nanosleep(64);
            __threadfence();
            // deterministic serial sum over the 48 partials, fixed order
            float mx = 0.f, my = 0.f, mz = 0.f;
            for (int i = 0; i < RB; i++) {
                mx += g_meanpart[(b * 3 + 0) * RB + i];
                my += g_meanpart[(b * 3 + 1) * RB + i];
                mz += g_meanpart[(b * 3 + 2) * RB + i];
            }
            mx *= (1.0f / (float)N);
            my *= (1.0f / (float)N);
            mz *= (1.0f / (float)N);
            smean[0] = mx; smean[1] = my; smean[2] = mz;
            if (part == 0) {
                g_mean[b * 3 + 0] = mx;
                g_mean[b * 3 + 1] = my;
                g_mean[b * 3 + 2] = mz;
            }
        }
        __syncthreads();

        const float mx = smean[0], my = smean[1], mz = smean[2];
        float best = 0.f;
#pragma unroll
        for (int k = 0; k < RADP; k++) {
            const int i = i0 + k * (RB * 256);
            if (i < N) {
                float x = sc[0][k][t] - mx;
                float y = sc[1][k][t] - my;
                float z = sc[2][k][t] - mz;
                best = fmaxf(best, x * x + y * y + z * z);
            }
        }
#pragma unroll
        for (int o = 16; o; o >>= 1)
            best = fmaxf(best, __shfl_xor_sync(0xffffffffu, best, o));
        if (lane == 0) sh[0][w] = best;
        __syncthreads();
        if (t == 0) {
            float m = sh[0][0];
            for (int i = 1; i < 8; i++) m = fmaxf(m, sh[0][i]);
            atomicMax(&g_radbits[b], __float_as_uint(m));  // nonneg: bit order == value order
            if (atomicAdd(&g_rdone[b], 1u) == (unsigned)(RB - 1)) {
                g_mdone[b] = 0u;       // reset handshake for next replay
                g_rdone[b] = 0u;
            }
        }
        return;
    }

    // ---- zero role: one warp per 64 rows ----
    // Coalesced count reads + ballot -> dirty masks; dirty 256B rows cleared
    // two at a time (half-warp each, STG.128).
    const int wg   = (bx - MR_BLKS) * (256 / 32) + (t >> 5);
    const int row0 = wg * 64;                    // < B*V
    const int lane = t & 31;
    const float4 z = make_float4(0.f, 0.f, 0.f, 0.f);

#pragma unroll
    for (int h = 0; h < 2; h++) {
        const int rbase = row0 + h * 32;
        const int c = g_count[rbase + lane];
        unsigned mask = __ballot_sync(0xffffffffu, c != 0);
        while (mask) {
            int r1 = __ffs(mask) - 1; mask &= mask - 1;
            int r2 = -1;
            if (mask) { r2 = __ffs(mask) - 1; mask &= mask - 1; }
            const int r = (lane < 16) ? r1 : r2;
            if (r >= 0) {
                float4* rp = reinterpret_cast<float4*>(
                    g_scratch + (size_t)(rbase + r) * C);
                rp[lane & 15] = z;
            }
        }
        if (c != 0) g_count[rbase + lane] = 0;
    }
}

// ---------------------------------------------------------------------------
__device__ __forceinline__ void red_add_v4(float* addr, float4 v) {
    asm volatile("red.global.add.v4.f32 [%0], {%1, %2, %3, %4};"
                 :: "l"(addr), "f"(v.x), "f"(v.y), "f"(v.z), "f"(v.w)
                 : "memory");
}
__device__ __forceinline__ void prefetch_l2(const void* p) {
    asm volatile("prefetch.global.L2 [%0];" :: "l"(p));
}
__device__ __forceinline__ void stcs_v4(float* addr, float4 v) {
    asm volatile("st.global.cs.v4.f32 [%0], {%1, %2, %3, %4};"
                 :: "l"(addr), "f"(v.x), "f"(v.y), "f"(v.z), "f"(v.w)
                 : "memory");
}

// Fused voxel-index + feature scatter. PDL secondary: before syncing on
// prep it loads its own coords into registers and prefetches chunk-0
// feature lines into L2 (inputs immutable -> safe pre-sync). Double-buffered
// smem tile, one barrier per chunk. Each RED covers 2 points x 64 channels
// with half-warp-contiguous 256B rows. Pinned at the REDG lane-issue floor
// (~12.8M v4 lanes x 1.29 cyc/lane / 148 SMs) -- SM-side restructuring
// verified not to move it (R5/R6/R7 identical).
__global__ __launch_bounds__(BP, 12) void scatter_kernel(
        const float* __restrict__ features,
        const float* __restrict__ coords,
        float* __restrict__ out_norm) {
    __shared__ float4 tile[2][CHUNK][17];  // stride 17 float4: conflict-free
    __shared__ int    sidx[BP];
    __shared__ float  sparm[4];            // mx, my, mz, denom

    const int b  = blockIdx.y;
    const int n0 = blockIdx.x * BP;
    const int t  = threadIdx.x;
    const int w    = t >> 5;
    const int lane = t & 31;

    const float* fb = features + (size_t)b * C * N;

    // --- pre-sync work on immutable inputs ---
    const int n = n0 + t;
    float cx = 0.f, cy = 0.f, cz = 0.f;
    if (n < N) {
        const float* p = coords + (size_t)b * 3 * N;
        cx = p[n];
        cy = p[n + N];
        cz = p[n + 2 * N];
    }
    if (lane < 16 && n0 < N)   // chunk-0 feature lines (128B each) into L2
        prefetch_l2(fb + (size_t)(16 * w + lane) * N + n0);

    cudaGridDependencySynchronize();   // prep (mean+radius+zero) done

    if (t < 3) sparm[t] = g_mean[b * 3 + t];
    if (t == 3) sparm[3] = 2.0f * sqrtf(__uint_as_float(g_radbits[b]));  // EPS=0
    __syncthreads();

    {   // prologue: voxel index for this block's points
        int idx = -1;
        if (n < N) {
            const float denom = sparm[3];
            float vx = (cx - sparm[0]) / denom + 0.5f;
            float vy = (cy - sparm[1]) / denom + 0.5f;
            float vz = (cz - sparm[2]) / denom + 0.5f;
            vx = fminf(fmaxf(vx * (float)R, 0.f), (float)(R - 1));
            vy = fminf(fmaxf(vy * (float)R, 0.f), (float)(R - 1));
            vz = fminf(fmaxf(vz * (float)R, 0.f), (float)(R - 1));

            float* on = out_norm + (size_t)b * 3 * N;
            on[n]         = vx;
            on[n + N]     = vy;
            on[n + 2 * N] = vz;

            // jnp.round == round-half-to-even == rintf
            idx = ((int)rintf(vx) * R + (int)rintf(vy)) * R + (int)rintf(vz);
            atomicAdd(&g_count[b * V + idx], 1);
        }
        sidx[t] = idx;
    }
    __syncthreads();

    const int half = lane >> 4;
    const int cl   = lane & 15;
    float* base = g_scratch + (size_t)b * V * C;

#pragma unroll
    for (int ch = 0; ch < BP / CHUNK; ch++) {
        const int buf = ch & 1;
        const int np  = n0 + ch * CHUNK + lane;
        if (np < N) {
            // warp w loads channels [16w, 16w+16) for its lane's point
            const float* f = fb + np + (size_t)(16 * w) * N;
#pragma unroll
            for (int q = 0; q < 4; q++) {
                float4 v;
                v.x = f[0];
                v.y = f[(size_t)N];
                v.z = f[(size_t)2 * N];
                v.w = f[(size_t)3 * N];
                tile[buf][lane][4 * w + q] = v;
                f += (size_t)4 * N;
            }
        }
        __syncthreads();

        // warp w reduces points [8w, 8w+8): 4 iters x 2 points
#pragma unroll
        for (int j = 0; j < 4; j++) {
            const int p  = 8 * w + 2 * j + half;
            const int vi = sidx[ch * CHUNK + p];
            if (vi >= 0)
                red_add_v4(base + (size_t)vi * C + 4 * cl, tile[buf][p][cl]);
        }
    }
}

// ---------------------------------------------------------------------------
// Transpose [b][v][c] -> [b][c][v] with count division. 64 voxels per block
// (measured-best shape: 15.9us @ occ 80%). Two 32-voxel subtiles share one
// mask/count phase; per-row read guard skips scratch reads of empty rows;
// empty tiles stream zeros; output uses streaming stores.
__global__ void finalize_kernel(float* __restrict__ out_grid) {
    __shared__ float    tile[2][32][65];
    __shared__ float    rinv[64];
    __shared__ unsigned s_mask[2];

    cudaGridDependencySynchronize();   // scatter done

    const int b  = blockIdx.x >> 9;             // V/64 = 512 chunks per batch
    const int v0 = (blockIdx.x & 511) * 64;
    const int t  = threadIdx.x;                 // 256 threads

    if (t < 64) {
        int c = g_count[b * V + v0 + t];
        rinv[t] = 1.0f / (float)(c > 1 ? c : 1);
        unsigned m = __ballot_sync(0xffffffffu, c != 0);
        if ((t & 31) == 0) s_mask[t >> 5] = m;
    }
    __syncthreads();
    const unsigned m0 = s_mask[0], m1 = s_mask[1];

    float* dst = out_grid + (size_t)b * C * V + v0;

    if (!(m0 | m1)) {   // fully empty: stream zeros, skip scratch entirely
        const float4 z = make_float4(0.f, 0.f, 0.f, 0.f);
#pragma unroll
        for (int k = 0; k < 4; k++) {
            int e  = t + k * 256;        // 0..1023
            int c  = e >> 4;             // channel 0..63
            int vg = (e & 15) * 4;       // voxel group 0..60
            stcs_v4(dst + (size_t)c * V + vg, z);
        }
        return;
    }

    const float4* src4 = reinterpret_cast<const float4*>(
        g_scratch + ((size_t)b * V + v0) * C);  // 1024 float4 (64 rows x 16)
#pragma unroll
    for (int k = 0; k < 4; k++) {
        int e   = t + k * 256;
        int row = e >> 4;                        // voxel 0..63
        unsigned mm = (row < 32) ? m0 : m1;
        float4 v = (mm & (1u << (row & 31))) ? src4[e]
                                             : make_float4(0.f, 0.f, 0.f, 0.f);
        int col = (e & 15) * 4;                  // channel 0..60
        float* tr = tile[row >> 5][row & 31];
        tr[col + 0] = v.x;
        tr[col + 1] = v.y;
        tr[col + 2] = v.z;
        tr[col + 3] = v.w;
    }
    __syncthreads();

    // store: subtile s handled by iterations k=2s,2s+1 with the proven
    // conflict-free pattern (bank bijective per warp)
#pragma unroll
    for (int k = 0; k < 4; k++) {
        int s  = k >> 1;                 // subtile 0/1
        int e  = t + (k & 1) * 256;      // 0..511 within subtile
        int c  = e >> 3;                 // channel 0..63
        int vg = (e & 7) * 4;            // voxel group 0..28 in subtile
        int vx = s * 32 + vg;            // absolute voxel in [0,64)
        float4 o;
        o.x = tile[s][vg + 0][c] * rinv[vx + 0];
        o.y = tile[s][vg + 1][c] * rinv[vx + 1];
        o.z = tile[s][vg + 2][c] * rinv[vx + 2];
        o.w = tile[s][vg + 3][c] * rinv[vx + 3];
        stcs_v4(dst + (size_t)c * V + vx, o);
    }
}

// ---------------------------------------------------------------------------
template <typename... Args>
static void launch_pdl(void (*kern)(Args...), dim3 grid, dim3 block,
                       Args... args) {
    cudaLaunchConfig_t cfg = {};
    cfg.gridDim = grid;
    cfg.blockDim = block;
    cudaLaunchAttribute attr[1];
    attr[0].id = cudaLaunchAttributeProgrammaticStreamSerialization;
    attr[0].val.programmaticStreamSerializationAllowed = 1;
    cfg.attrs = attr;
    cfg.numAttrs = 1;
    cudaLaunchKernelEx(&cfg, kern, args...);
}

extern "C" void kernel_launch(void* const* d_in, const int* in_sizes, int n_in,
                              void* d_out, int out_size) {
    const float* features = (const float*)d_in[0];
    const float* coords   = (const float*)d_in[1];
    float* out_grid = (float*)d_out;                      // [B,C,V]
    float* out_norm = (float*)d_out + (size_t)B * C * V;  // [B,3,N]

    prep_kernel<<<MR_BLKS + ZERO_BLKS, 256>>>(coords);
    launch_pdl(scatter_kernel, dim3((N + BP - 1) / BP, B), dim3(BP),
               features, coords, out_norm);
    launch_pdl(finalize_kernel, dim3(B * (V / 64)), dim3(256), out_grid);
}

// round 16
// speedup vs baseline: 1.0382x; 1.0382x over previous
#include <cuda_runtime.h>
#include <math.h>

// Problem constants (features [8,64,100000], coords [8,3,100000], R=32)
constexpr int B = 8;
constexpr int C = 64;
constexpr int N = 100000;
constexpr int R = 32;
constexpr int V = R * R * R;   // 32768
constexpr int BP = 128;        // points per scatter block
constexpr int CHUNK = 32;      // points staged per chunk
constexpr int RB = 48;         // mean+radius blocks per batch
constexpr int RADP = 9;        // points per thread (48*256*9 >= N)
constexpr int MR_BLKS  = B * RB;                 // 384
constexpr int ZERO_BLKS = (B * V) / 256;         // 1024 (256 rows / 8-warp block)

// Scratch (allocation-free rule: __device__ globals). Zero-initialized at
// module load. The guarded zero keeps the invariant "rows with count==0 are
// all-zero" across graph replays by clearing exactly the dirty rows.
__device__ float        g_scratch[(size_t)B * V * C];  // [b][voxel][c]  64 MB
__device__ int          g_count[B * V];
__device__ float        g_meanpart[B * 3 * RB];
__device__ float        g_mean[B * 3];
__device__ unsigned int g_radbits[B];
__device__ unsigned int g_mdone[B];    // mean partials published per batch
__device__ unsigned int g_rdone[B];    // finished blocks per batch

// ---------------------------------------------------------------------------
// One fused launch, two block roles (R14 config -- measured best -- with one
// change: the post-spin 144-load serial chain is replaced by a parallel
// coalesced load into smem + the SAME fixed-order serial sum from smem).
//   [0, MR_BLKS)  single-pass mean+radius: preload <=9 points/thread into
//                 registers, publish mean partial, spin for the batch's 48
//                 partials, then radius max FROM THE SAME REGISTERS.
//   [MR_BLKS, +ZERO_BLKS)  clear dirty scratch rows + counts (warp/32 rows).
// Mean = fixed-order serial sum of 48 partials (deterministic, identical in
// every block); radius via order-independent atomicMax; handshake counters
// reset by last finisher per batch.
__global__ void prep_kernel(const float* __restrict__ coords) {
    const int bx = blockIdx.x;
    const int t  = threadIdx.x;

    if (bx < MR_BLKS) {            // ---- mean + radius, one coord pass ----
        const int b    = bx / RB;
        const int part = bx % RB;
        const float* px = coords + (size_t)b * 3 * N;

        float xs[RADP], ys[RADP], zs[RADP];
        float sx = 0.f, sy = 0.f, sz = 0.f;
        const int i0 = part * 256 + t;
#pragma unroll
        for (int k = 0; k < RADP; k++) {
            const int i = i0 + k * (RB * 256);
            const bool v = i < N;
            float x = v ? px[i]         : 0.f;
            float y = v ? px[i + N]     : 0.f;
            float z = v ? px[i + 2 * N] : 0.f;
            xs[k] = x; ys[k] = y; zs[k] = z;
            sx += x; sy += y; sz += z;
        }
#pragma unroll
        for (int o = 16; o; o >>= 1) {
            sx += __shfl_xor_sync(0xffffffffu, sx, o);
            sy += __shfl_xor_sync(0xffffffffu, sy, o);
            sz += __shfl_xor_sync(0xffffffffu, sz, o);
        }
        __shared__ float sh[3][8];
        __shared__ float spart[3 * RB];   // parallel-loaded partials
        __shared__ float smean[3];
        const int lane = t & 31, w = t >> 5;
        if (lane == 0) { sh[0][w] = sx; sh[1][w] = sy; sh[2][w] = sz; }
        __syncthreads();

        if (t == 0) {
            float ax = 0.f, ay = 0.f, az = 0.f;
            for (int i = 0; i < 8; i++) { ax += sh[0][i]; ay += sh[1][i]; az += sh[2][i]; }
            if (part == 0) g_radbits[b] = 0u;        // before publish: ordered
            g_meanpart[(b * 3 + 0) * RB + part] = ax;
            g_meanpart[(b * 3 + 1) * RB + part] = ay;
            g_meanpart[(b * 3 + 2) * RB + part] = az;
            __threadfence();
            atomicAdd(&g_mdone[b], 1u);              // publish
            while (atomicAdd(&g_mdone[b], 0u) < (unsigned)RB)
                __nanosleep(64);
        }
        __syncthreads();   // all threads ordered after t0's observation

        // parallel coalesced load of all 144 partials (first use of these
        // lines in this kernel -> L1 cannot be stale; L2 holds published data)
        if (t < 3 * RB)
            spart[t] = g_meanpart[b * 3 * RB + t];
        __syncthreads();

        if (t == 0) {
            // SAME fixed-order serial sum as before, now from smem
            float mx = 0.f, my = 0.f, mz = 0.f;
            for (int i = 0; i < RB; i++) {
                mx += spart[0 * RB + i];
                my += spart[1 * RB + i];
                mz += spart[2 * RB + i];
            }
            mx *= (1.0f / (float)N);
            my *= (1.0f / (float)N);
            mz *= (1.0f / (float)N);
            smean[0] = mx; smean[1] = my; smean[2] = mz;
            if (part == 0) {
                g_mean[b * 3 + 0] = mx;
                g_mean[b * 3 + 1] = my;
                g_mean[b * 3 + 2] = mz;
            }
        }
        __syncthreads();

        const float mx = smean[0], my = smean[1], mz = smean[2];
        float best = 0.f;
#pragma unroll
        for (int k = 0; k < RADP; k++) {
            const int i = i0 + k * (RB * 256);
            if (i < N) {
                float x = xs[k] - mx, y = ys[k] - my, z = zs[k] - mz;
                best = fmaxf(best, x * x + y * y + z * z);
            }
        }
#pragma unroll
        for (int o = 16; o; o >>= 1)
            best = fmaxf(best, __shfl_xor_sync(0xffffffffu, best, o));
        if (lane == 0) sh[0][w] = best;
        __syncthreads();
        if (t == 0) {
            float m = sh[0][0];
            for (int i = 1; i < 8; i++) m = fmaxf(m, sh[0][i]);
            atomicMax(&g_radbits[b], __float_as_uint(m));  // nonneg: bit order == value order
            if (atomicAdd(&g_rdone[b], 1u) == (unsigned)(RB - 1)) {
                g_mdone[b] = 0u;       // reset handshake for next replay
                g_rdone[b] = 0u;
            }
        }
        return;
    }

    // ---- zero role: one warp per 32 rows ----
    // Coalesced 32-wide count read, ballot -> dirty mask, then clear dirty
    // 256B rows two at a time (half-warp each, STG.128).
    const int wg   = (bx - MR_BLKS) * (256 / 32) + (t >> 5);
    const int row0 = wg * 32;                    // < B*V
    const int lane = t & 31;

    const int c = g_count[row0 + lane];
    unsigned mask = __ballot_sync(0xffffffffu, c != 0);
    const float4 z = make_float4(0.f, 0.f, 0.f, 0.f);
    while (mask) {
        int r1 = __ffs(mask) - 1; mask &= mask - 1;
        int r2 = -1;
        if (mask) { r2 = __ffs(mask) - 1; mask &= mask - 1; }
        const int r = (lane < 16) ? r1 : r2;
        if (r >= 0) {
            float4* rp = reinterpret_cast<float4*>(
                g_scratch + (size_t)(row0 + r) * C);
            rp[lane & 15] = z;
        }
    }
    if (c != 0) g_count[row0 + lane] = 0;
}

// ---------------------------------------------------------------------------
__device__ __forceinline__ void red_add_v4(float* addr, float4 v) {
    asm volatile("red.global.add.v4.f32 [%0], {%1, %2, %3, %4};"
                 :: "l"(addr), "f"(v.x), "f"(v.y), "f"(v.z), "f"(v.w)
                 : "memory");
}
__device__ __forceinline__ void prefetch_l2(const void* p) {
    asm volatile("prefetch.global.L2 [%0];" :: "l"(p));
}
__device__ __forceinline__ void stcs_v4(float* addr, float4 v) {
    asm volatile("st.global.cs.v4.f32 [%0], {%1, %2, %3, %4};"
                 :: "l"(addr), "f"(v.x), "f"(v.y), "f"(v.z), "f"(v.w)
                 : "memory");
}

// Fused voxel-index + feature scatter. PDL secondary: before syncing on
// prep it loads its own coords into registers and prefetches chunk-0
// feature lines into L2 (inputs immutable -> safe pre-sync). Double-buffered
// smem tile, one barrier per chunk. Each RED covers 2 points x 64 channels
// with half-warp-contiguous 256B rows. Pinned at the REDG lane-issue floor
// (~12.8M v4 lanes x 1.29 cyc/lane / 148 SMs) -- SM-side restructuring
// verified not to move it (R5/R6/R7 identical).
__global__ __launch_bounds__(BP, 12) void scatter_kernel(
        const float* __restrict__ features,
        const float* __restrict__ coords,
        float* __restrict__ out_norm) {
    __shared__ float4 tile[2][CHUNK][17];  // stride 17 float4: conflict-free
    __shared__ int    sidx[BP];
    __shared__ float  sparm[4];            // mx, my, mz, denom

    const int b  = blockIdx.y;
    const int n0 = blockIdx.x * BP;
    const int t  = threadIdx.x;
    const int w    = t >> 5;
    const int lane = t & 31;

    const float* fb = features + (size_t)b * C * N;

    // --- pre-sync work on immutable inputs ---
    const int n = n0 + t;
    float cx = 0.f, cy = 0.f, cz = 0.f;
    if (n < N) {
        const float* p = coords + (size_t)b * 3 * N;
        cx = p[n];
        cy = p[n + N];
        cz = p[n + 2 * N];
    }
    if (lane < 16 && n0 < N)   // chunk-0 feature lines (128B each) into L2
        prefetch_l2(fb + (size_t)(16 * w + lane) * N + n0);

    cudaGridDependencySynchronize();   // prep (mean+radius+zero) done

    if (t < 3) sparm[t] = g_mean[b * 3 + t];
    if (t == 3) sparm[3] = 2.0f * sqrtf(__uint_as_float(g_radbits[b]));  // EPS=0
    __syncthreads();

    {   // prologue: voxel index for this block's points
        int idx = -1;
        if (n < N) {
            const float denom = sparm[3];
            float vx = (cx - sparm[0]) / denom + 0.5f;
            float vy = (cy - sparm[1]) / denom + 0.5f;
            float vz = (cz - sparm[2]) / denom + 0.5f;
            vx = fminf(fmaxf(vx * (float)R, 0.f), (float)(R - 1));
            vy = fminf(fmaxf(vy * (float)R, 0.f), (float)(R - 1));
            vz = fminf(fmaxf(vz * (float)R, 0.f), (float)(R - 1));

            float* on = out_norm + (size_t)b * 3 * N;
            on[n]         = vx;
            on[n + N]     = vy;
            on[n + 2 * N] = vz;

            // jnp.round == round-half-to-even == rintf
            idx = ((int)rintf(vx) * R + (int)rintf(vy)) * R + (int)rintf(vz);
            atomicAdd(&g_count[b * V + idx], 1);
        }
        sidx[t] = idx;
    }
    __syncthreads();

    const int half = lane >> 4;
    const int cl   = lane & 15;
    float* base = g_scratch + (size_t)b * V * C;

#pragma unroll
    for (int ch = 0; ch < BP / CHUNK; ch++) {
        const int buf = ch & 1;
        const int np  = n0 + ch * CHUNK + lane;
        if (np < N) {
            // warp w loads channels [16w, 16w+16) for its lane's point
            const float* f = fb + np + (size_t)(16 * w) * N;
#pragma unroll
            for (int q = 0; q < 4; q++) {
                float4 v;
                v.x = f[0];
                v.y = f[(size_t)N];
                v.z = f[(size_t)2 * N];
                v.w = f[(size_t)3 * N];
                tile[buf][lane][4 * w + q] = v;
                f += (size_t)4 * N;
            }
        }
        __syncthreads();

        // warp w reduces points [8w, 8w+8): 4 iters x 2 points
#pragma unroll
        for (int j = 0; j < 4; j++) {
            const int p  = 8 * w + 2 * j + half;
            const int vi = sidx[ch * CHUNK + p];
            if (vi >= 0)
                red_add_v4(base + (size_t)vi * C + 4 * cl, tile[buf][p][cl]);
        }
    }
}

// ---------------------------------------------------------------------------
// Transpose [b][v][c] -> [b][c][v] with count division. 64 voxels per block
// (measured-best shape: 15.9us @ occ 80%). Two 32-voxel subtiles share one
// mask/count phase; per-row read guard skips scratch reads of empty rows;
// empty tiles stream zeros; output uses streaming stores.
__global__ void finalize_kernel(float* __restrict__ out_grid) {
    __shared__ float    tile[2][32][65];
    __shared__ float    rinv[64];
    __shared__ unsigned s_mask[2];

    cudaGridDependencySynchronize();   // scatter done

    const int b  = blockIdx.x >> 9;             // V/64 = 512 chunks per batch
    const int v0 = (blockIdx.x & 511) * 64;
    const int t  = threadIdx.x;                 // 256 threads

    if (t < 64) {
        int c = g_count[b * V + v0 + t];
        rinv[t] = 1.0f / (float)(c > 1 ? c : 1);
        unsigned m = __ballot_sync(0xffffffffu, c != 0);
        if ((t & 31) == 0) s_mask[t >> 5] = m;
    }
    __syncthreads();
    const unsigned m0 = s_mask[0], m1 = s_mask[1];

    float* dst = out_grid + (size_t)b * C * V + v0;

    if (!(m0 | m1)) {   // fully empty: stream zeros, skip scratch entirely
        const float4 z = make_float4(0.f, 0.f, 0.f, 0.f);
#pragma unroll
        for (int k = 0; k < 4; k++) {
            int e  = t + k * 256;        // 0..1023
            int c  = e >> 4;             // channel 0..63
            int vg = (e & 15) * 4;       // voxel group 0..60
            stcs_v4(dst + (size_t)c * V + vg, z);
        }
        return;
    }

    const float4* src4 = reinterpret_cast<const float4*>(
        g_scratch + ((size_t)b * V + v0) * C);  // 1024 float4 (64 rows x 16)
#pragma unroll
    for (int k = 0; k < 4; k++) {
        int e   = t + k * 256;
        int row = e >> 4;                        // voxel 0..63
        unsigned mm = (row < 32) ? m0 : m1;
        float4 v = (mm & (1u << (row & 31))) ? src4[e]
                                             : make_float4(0.f, 0.f, 0.f, 0.f);
        int col = (e & 15) * 4;                  // channel 0..60
        float* tr = tile[row >> 5][row & 31];
        tr[col + 0] = v.x;
        tr[col + 1] = v.y;
        tr[col + 2] = v.z;
        tr[col + 3] = v.w;
    }
    __syncthreads();

    // store: subtile s handled by iterations k=2s,2s+1 with the proven
    // conflict-free pattern (bank bijective per warp)
#pragma unroll
    for (int k = 0; k < 4; k++) {
        int s  = k >> 1;                 // subtile 0/1
        int e  = t + (k & 1) * 256;      // 0..511 within subtile
        int c  = e >> 3;                 // channel 0..63
        int vg = (e & 7) * 4;            // voxel group 0..28 in subtile
        int vx = s * 32 + vg;            // absolute voxel in [0,64)
        float4 o;
        o.x = tile[s][vg + 0][c] * rinv[vx + 0];
        o.y = tile[s][vg + 1][c] * rinv[vx + 1];
        o.z = tile[s][vg + 2][c] * rinv[vx + 2];
        o.w = tile[s][vg + 3][c] * rinv[vx + 3];
        stcs_v4(dst + (size_t)c * V + vx, o);
    }
}

// ---------------------------------------------------------------------------
template <typename... Args>
static void launch_pdl(void (*kern)(Args...), dim3 grid, dim3 block,
                       Args... args) {
    cudaLaunchConfig_t cfg = {};
    cfg.gridDim = grid;
    cfg.blockDim = block;
    cudaLaunchAttribute attr[1];
    attr[0].id = cudaLaunchAttributeProgrammaticStreamSerialization;
    attr[0].val.programmaticStreamSerializationAllowed = 1;
    cfg.attrs = attr;
    cfg.numAttrs = 1;
    cudaLaunchKernelEx(&cfg, kern, args...);
}

extern "C" void kernel_launch(void* const* d_in, const int* in_sizes, int n_in,
                              void* d_out, int out_size) {
    const float* features = (const float*)d_in[0];
    const float* coords   = (const float*)d_in[1];
    float* out_grid = (float*)d_out;                      // [B,C,V]
    float* out_norm = (float*)d_out + (size_t)B * C * V;  // [B,3,N]

    prep_kernel<<<MR_BLKS + ZERO_BLKS, 256>>>(coords);
    launch_pdl(scatter_kernel, dim3((N + BP - 1) / BP, B), dim3(BP),
               features, coords, out_norm);
    launch_pdl(finalize_kernel, dim3(B * (V / 64)), dim3(256), out_grid);
}